// round 6
// baseline (speedup 1.0000x reference)
#include <cuda_runtime.h>
#include <cuda_bf16.h>

// Persistent kernel: grid = 4*148 blocks of 256 threads (32 warps/SM).
// Each warp loops over chunks of 8 edges (stride = total warps * 8), with the
// NEXT chunk's index load issued before the current chunk's gathers/compute,
// hiding the index-load -> gather dependency chain under the previous
// iteration's work.
// Within a chunk: 8-lane group g handles edges e0+2g, e0+2g+1; each lane
// issues 16 independent LDG.128 gathers; two 3-level butterflies; group
// leader stores a float2.
__global__ void __launch_bounds__(256) edge_dot_kernel(
    const float* __restrict__ h,
    const int* __restrict__ src,
    const int* __restrict__ dst,
    float* __restrict__ out,
    int n_edges)
{
    const int wib  = threadIdx.x >> 5;
    const int lane = threadIdx.x & 31;
    const int g = lane >> 3;        // group (0..3)
    const int t = lane & 7;         // sublane in group
    const unsigned FULL = 0xFFFFFFFFu;

    const int W  = blockIdx.x * 8 + wib;      // global warp id
    const int stride = gridDim.x * 8 * 8;     // edges per sweep (warps*8)

    int e0 = W * 8;
    if (e0 >= n_edges) return;

    // prefetch indices for first chunk: lanes 0-7 src, lanes 8-15 dst
    int idx = 0;
    if (lane < 16) {
        int ei = e0 + (lane & 7);
        if (ei < n_edges)
            idx = (lane < 8) ? src[ei] : dst[ei];
    }

    while (true) {
        // ---- prefetch indices for next chunk (issues before current drain)
        int e0n = e0 + stride;
        int idx_next = 0;
        if (e0n < n_edges && lane < 16) {
            int ei = e0n + (lane & 7);
            if (ei < n_edges)
                idx_next = (lane < 8) ? src[ei] : dst[ei];
        }

        // ---- current chunk
        int sA = __shfl_sync(FULL, idx, 2 * g);
        int sB = __shfl_sync(FULL, idx, 2 * g + 1);
        int dA = __shfl_sync(FULL, idx, 8 + 2 * g);
        int dB = __shfl_sync(FULL, idx, 8 + 2 * g + 1);

        const float4* psA = reinterpret_cast<const float4*>(h) + (size_t)sA * 32 + t;
        const float4* pdA = reinterpret_cast<const float4*>(h) + (size_t)dA * 32 + t;
        const float4* psB = reinterpret_cast<const float4*>(h) + (size_t)sB * 32 + t;
        const float4* pdB = reinterpret_cast<const float4*>(h) + (size_t)dB * 32 + t;

        float4 a0 = __ldg(psA);      float4 a1 = __ldg(psA + 8);
        float4 a2 = __ldg(psA + 16); float4 a3 = __ldg(psA + 24);
        float4 b0 = __ldg(pdA);      float4 b1 = __ldg(pdA + 8);
        float4 b2 = __ldg(pdA + 16); float4 b3 = __ldg(pdA + 24);
        float4 c0 = __ldg(psB);      float4 c1 = __ldg(psB + 8);
        float4 c2 = __ldg(psB + 16); float4 c3 = __ldg(psB + 24);
        float4 f0 = __ldg(pdB);      float4 f1 = __ldg(pdB + 8);
        float4 f2 = __ldg(pdB + 16); float4 f3 = __ldg(pdB + 24);

        float accA = a0.x * b0.x;
        accA = fmaf(a0.y, b0.y, accA); accA = fmaf(a0.z, b0.z, accA); accA = fmaf(a0.w, b0.w, accA);
        accA = fmaf(a1.x, b1.x, accA); accA = fmaf(a1.y, b1.y, accA);
        accA = fmaf(a1.z, b1.z, accA); accA = fmaf(a1.w, b1.w, accA);
        accA = fmaf(a2.x, b2.x, accA); accA = fmaf(a2.y, b2.y, accA);
        accA = fmaf(a2.z, b2.z, accA); accA = fmaf(a2.w, b2.w, accA);
        accA = fmaf(a3.x, b3.x, accA); accA = fmaf(a3.y, b3.y, accA);
        accA = fmaf(a3.z, b3.z, accA); accA = fmaf(a3.w, b3.w, accA);

        float accB = c0.x * f0.x;
        accB = fmaf(c0.y, f0.y, accB); accB = fmaf(c0.z, f0.z, accB); accB = fmaf(c0.w, f0.w, accB);
        accB = fmaf(c1.x, f1.x, accB); accB = fmaf(c1.y, f1.y, accB);
        accB = fmaf(c1.z, f1.z, accB); accB = fmaf(c1.w, f1.w, accB);
        accB = fmaf(c2.x, f2.x, accB); accB = fmaf(c2.y, f2.y, accB);
        accB = fmaf(c2.z, f2.z, accB); accB = fmaf(c2.w, f2.w, accB);
        accB = fmaf(c3.x, f3.x, accB); accB = fmaf(c3.y, f3.y, accB);
        accB = fmaf(c3.z, f3.z, accB); accB = fmaf(c3.w, f3.w, accB);

        accA += __shfl_xor_sync(FULL, accA, 4);
        accB += __shfl_xor_sync(FULL, accB, 4);
        accA += __shfl_xor_sync(FULL, accA, 2);
        accB += __shfl_xor_sync(FULL, accB, 2);
        accA += __shfl_xor_sync(FULL, accA, 1);
        accB += __shfl_xor_sync(FULL, accB, 1);

        if (t == 0) {
            int eA = e0 + 2 * g;
            if (eA + 1 < n_edges) {
                *reinterpret_cast<float2*>(out + eA) = make_float2(accA, accB);
            } else if (eA < n_edges) {
                out[eA] = accA;
            }
        }

        if (e0n >= n_edges) break;
        e0 = e0n;
        idx = idx_next;
    }
}

extern "C" void kernel_launch(void* const* d_in, const int* in_sizes, int n_in,
                              void* d_out, int out_size)
{
    const float* h   = (const float*)d_in[0];
    const int*   src = (const int*)d_in[1];
    const int*   dst = (const int*)d_in[2];
    float* out = (float*)d_out;

    int n_edges = in_sizes[1];               // E = 640000

    int grid = 4 * 148;                      // persistent: 32 warps/SM
    // cap grid so every warp has at least one chunk
    int max_grid = (n_edges + 63) / 64;
    if (grid > max_grid) grid = max_grid;

    edge_dot_kernel<<<grid, 256>>>(h, src, dst, out, n_edges);
}

// round 7
// speedup vs baseline: 1.0437x; 1.0437x over previous
#include <cuda_runtime.h>
#include <cuda_bf16.h>

// Persistent kernel, 6 blocks/SM (grid = 6*148 = 888, 48 warps/SM at 40 regs).
// Each warp loops over chunks of 8 edges (stride = total warps * 8), with the
// NEXT chunk's index load issued before the current chunk's gathers/compute.
// Within a chunk: 8-lane group g handles edges e0+2g, e0+2g+1; each lane
// issues 16 independent LDG.128 gathers; two 3-level butterflies; group
// leader stores a float2.
__global__ void __launch_bounds__(256, 6) edge_dot_kernel(
    const float* __restrict__ h,
    const int* __restrict__ src,
    const int* __restrict__ dst,
    float* __restrict__ out,
    int n_edges)
{
    const int wib  = threadIdx.x >> 5;
    const int lane = threadIdx.x & 31;
    const int g = lane >> 3;        // group (0..3)
    const int t = lane & 7;         // sublane in group
    const unsigned FULL = 0xFFFFFFFFu;

    const int W  = blockIdx.x * 8 + wib;      // global warp id
    const int stride = gridDim.x * 8 * 8;     // edges per sweep (warps*8)

    int e0 = W * 8;
    if (e0 >= n_edges) return;

    // prefetch indices for first chunk: lanes 0-7 src, lanes 8-15 dst
    int idx = 0;
    if (lane < 16) {
        int ei = e0 + (lane & 7);
        if (ei < n_edges)
            idx = (lane < 8) ? src[ei] : dst[ei];
    }

    while (true) {
        // ---- prefetch indices for next chunk (issues before current drain)
        int e0n = e0 + stride;
        int idx_next = 0;
        if (e0n < n_edges && lane < 16) {
            int ei = e0n + (lane & 7);
            if (ei < n_edges)
                idx_next = (lane < 8) ? src[ei] : dst[ei];
        }

        // ---- current chunk
        int sA = __shfl_sync(FULL, idx, 2 * g);
        int sB = __shfl_sync(FULL, idx, 2 * g + 1);
        int dA = __shfl_sync(FULL, idx, 8 + 2 * g);
        int dB = __shfl_sync(FULL, idx, 8 + 2 * g + 1);

        const float4* psA = reinterpret_cast<const float4*>(h) + (size_t)sA * 32 + t;
        const float4* pdA = reinterpret_cast<const float4*>(h) + (size_t)dA * 32 + t;
        const float4* psB = reinterpret_cast<const float4*>(h) + (size_t)sB * 32 + t;
        const float4* pdB = reinterpret_cast<const float4*>(h) + (size_t)dB * 32 + t;

        float4 a0 = __ldg(psA);      float4 a1 = __ldg(psA + 8);
        float4 a2 = __ldg(psA + 16); float4 a3 = __ldg(psA + 24);
        float4 b0 = __ldg(pdA);      float4 b1 = __ldg(pdA + 8);
        float4 b2 = __ldg(pdA + 16); float4 b3 = __ldg(pdA + 24);
        float4 c0 = __ldg(psB);      float4 c1 = __ldg(psB + 8);
        float4 c2 = __ldg(psB + 16); float4 c3 = __ldg(psB + 24);
        float4 f0 = __ldg(pdB);      float4 f1 = __ldg(pdB + 8);
        float4 f2 = __ldg(pdB + 16); float4 f3 = __ldg(pdB + 24);

        float accA = a0.x * b0.x;
        accA = fmaf(a0.y, b0.y, accA); accA = fmaf(a0.z, b0.z, accA); accA = fmaf(a0.w, b0.w, accA);
        accA = fmaf(a1.x, b1.x, accA); accA = fmaf(a1.y, b1.y, accA);
        accA = fmaf(a1.z, b1.z, accA); accA = fmaf(a1.w, b1.w, accA);
        accA = fmaf(a2.x, b2.x, accA); accA = fmaf(a2.y, b2.y, accA);
        accA = fmaf(a2.z, b2.z, accA); accA = fmaf(a2.w, b2.w, accA);
        accA = fmaf(a3.x, b3.x, accA); accA = fmaf(a3.y, b3.y, accA);
        accA = fmaf(a3.z, b3.z, accA); accA = fmaf(a3.w, b3.w, accA);

        float accB = c0.x * f0.x;
        accB = fmaf(c0.y, f0.y, accB); accB = fmaf(c0.z, f0.z, accB); accB = fmaf(c0.w, f0.w, accB);
        accB = fmaf(c1.x, f1.x, accB); accB = fmaf(c1.y, f1.y, accB);
        accB = fmaf(c1.z, f1.z, accB); accB = fmaf(c1.w, f1.w, accB);
        accB = fmaf(c2.x, f2.x, accB); accB = fmaf(c2.y, f2.y, accB);
        accB = fmaf(c2.z, f2.z, accB); accB = fmaf(c2.w, f2.w, accB);
        accB = fmaf(c3.x, f3.x, accB); accB = fmaf(c3.y, f3.y, accB);
        accB = fmaf(c3.z, f3.z, accB); accB = fmaf(c3.w, f3.w, accB);

        accA += __shfl_xor_sync(FULL, accA, 4);
        accB += __shfl_xor_sync(FULL, accB, 4);
        accA += __shfl_xor_sync(FULL, accA, 2);
        accB += __shfl_xor_sync(FULL, accB, 2);
        accA += __shfl_xor_sync(FULL, accA, 1);
        accB += __shfl_xor_sync(FULL, accB, 1);

        if (t == 0) {
            int eA = e0 + 2 * g;
            if (eA + 1 < n_edges) {
                *reinterpret_cast<float2*>(out + eA) = make_float2(accA, accB);
            } else if (eA < n_edges) {
                out[eA] = accA;
            }
        }

        if (e0n >= n_edges) break;
        e0 = e0n;
        idx = idx_next;
    }
}

extern "C" void kernel_launch(void* const* d_in, const int* in_sizes, int n_in,
                              void* d_out, int out_size)
{
    const float* h   = (const float*)d_in[0];
    const int*   src = (const int*)d_in[1];
    const int*   dst = (const int*)d_in[2];
    float* out = (float*)d_out;

    int n_edges = in_sizes[1];               // E = 640000

    int grid = 6 * 148;                      // persistent: 48 warps/SM
    // cap grid so every warp has at least one chunk
    int max_grid = (n_edges + 63) / 64;
    if (grid > max_grid) grid = max_grid;

    edge_dot_kernel<<<grid, 256>>>(h, src, dst, out, n_edges);
}